// round 16
// baseline (speedup 1.0000x reference)
#include <cuda_runtime.h>
#include <math.h>
#include <stdint.h>
#include <stddef.h>

// ---------------------------------------------------------------------------
// AugmentedLstm: B=64, T=512, D=512, H=512
//   Kernel A: proj = X[32768,512] @ w_in^T -> [32768,3072] (+bias), fp32 FFMA2
//   Kernel B: persistent 128-CTA recurrence, 256 thr/CTA (R14 base, 2 warps
//             per SMSP via k-half split) +
//             (1) INTERLEAVED batch->warp map (warp q owns pairs q,q+4..q+28)
//                 so live work stays balanced as sorted lengths expire;
//                 physical SMEM slots stay contiguous per warp (permutation).
//             (2) merged end barrier: sh_red double-buffered by t-parity;
//                 only kh0 (128 thr) barriers before the group signal.
// ---------------------------------------------------------------------------

#define BDIM 64
#define TDIM 512
#define HDIM 512
#define MTOT (BDIM * TDIM)   // 32768
#define NTOT (6 * HDIM)      // 3072
#define NCTA_B 128

// packed fp32x2 FMA (sm_100+/sm_103a PTX; ptxas never emits it from C++)
#define FMA2(d, a, b) asm("fma.rn.f32x2 %0, %1, %2, %0;" : "+l"(d) : "l"(a), "l"(b))

__device__ __forceinline__ float f2lo(unsigned long long v) {
    return __uint_as_float((unsigned)(v & 0xffffffffull));
}
__device__ __forceinline__ float f2hi(unsigned long long v) {
    return __uint_as_float((unsigned)(v >> 32));
}
__device__ __forceinline__ float sigm(float x) { return 1.0f / (1.0f + expf(-x)); }

// ---- global scratch (no runtime allocation allowed) ----
__device__ float g_proj[(size_t)MTOT * NTOT];     // 402 MB input projections
__device__ float g_hbuf[2][BDIM * HDIM];          // double-buffered h state
__device__ unsigned int g_cnt[8];                 // per-group step counters

__device__ __forceinline__ int read_len(const int* L, int b) {
    return (L[1] == 0) ? L[2 * b] : L[b];   // int64 vs int32 auto-detect
}

__device__ __forceinline__ void signal_release(unsigned* p) {
    unsigned t;
    asm volatile("atom.add.release.gpu.u32 %0, [%1], 1;" : "=r"(t) : "l"(p) : "memory");
}
__device__ __forceinline__ unsigned ld_acq(unsigned* p) {
    unsigned v;
    asm volatile("ld.acquire.gpu.u32 %0, [%1];" : "=r"(v) : "l"(p) : "memory");
    return v;
}
__device__ __forceinline__ void pollw(unsigned* p, unsigned tgt) {
    while ((int)(ld_acq(p) - tgt) < 0) { }
}

__device__ __forceinline__ void cpasync16(uint32_t dst, const float* src) {
    asm volatile("cp.async.cg.shared.global [%0], [%1], 16;" :: "r"(dst), "l"(src));
}
#define CP_COMMIT()  asm volatile("cp.async.commit_group;" ::: "memory")
#define CP_WAITG(n)  asm volatile("cp.async.wait_group " #n ";" ::: "memory")
#define NBAR(id, cnt) asm volatile("bar.sync %0, %1;" :: "r"(id), "r"(cnt) : "memory")

// ---------------------------------------------------------------------------
// Kernel A: 128x128 tile SGEMM with FFMA2 (A duplicated in SMEM so a2=(a,a))
// ---------------------------------------------------------------------------
__global__ __launch_bounds__(256)
void proj_kernel(const float* __restrict__ X, const int* __restrict__ L,
                 const float* __restrict__ W, const float* __restrict__ Bi)
{
    __shared__ float As2[32 * 256];   // [k][2*m] duplicated pairs
    __shared__ float Bs[32 * 128];    // [k][n]
    const int n0 = blockIdx.x * 128;
    const int m0 = blockIdx.y * 128;
    const int bidx = m0 >> 9;         // batch of this M tile (512 % 128 == 0)
    const int t0 = m0 & 511;
    if (read_len(L, bidx) <= t0) return;   // whole tile past this batch's length

    const int tid = threadIdx.x;
    const int tm = tid >> 4;          // 0..15
    const int tn = tid & 15;          // 0..15

    unsigned long long acc[8][4] = {};

    float4 ra[4], rb[4];
    #pragma unroll
    for (int i = 0; i < 4; i++) {     // prime chunk 0
        int idx4 = tid + (i << 8);
        int rr = idx4 >> 3, kq = idx4 & 7;
        ra[i] = *(const float4*)&X[(size_t)(m0 + rr) * 512 + (kq << 2)];
        rb[i] = *(const float4*)&W[(size_t)(n0 + rr) * 512 + (kq << 2)];
    }

    for (int kc = 0; kc < 16; kc++) {
        __syncthreads();
        #pragma unroll
        for (int i = 0; i < 4; i++) {
            int idx4 = tid + (i << 8);
            int rr = idx4 >> 3, kq = idx4 & 7;
            float4 v = ra[i];
            float2 d;
            d.x = v.x; d.y = v.x; *(float2*)&As2[((kq << 2) + 0) * 256 + 2 * rr] = d;
            d.x = v.y; d.y = v.y; *(float2*)&As2[((kq << 2) + 1) * 256 + 2 * rr] = d;
            d.x = v.z; d.y = v.z; *(float2*)&As2[((kq << 2) + 2) * 256 + 2 * rr] = d;
            d.x = v.w; d.y = v.w; *(float2*)&As2[((kq << 2) + 3) * 256 + 2 * rr] = d;
            float4 w4 = rb[i];
            Bs[((kq << 2) + 0) * 128 + rr] = w4.x;
            Bs[((kq << 2) + 1) * 128 + rr] = w4.y;
            Bs[((kq << 2) + 2) * 128 + rr] = w4.z;
            Bs[((kq << 2) + 3) * 128 + rr] = w4.w;
        }
        __syncthreads();
        if (kc < 15) {   // prefetch next chunk into registers during compute
            int kb = (kc + 1) << 5;
            #pragma unroll
            for (int i = 0; i < 4; i++) {
                int idx4 = tid + (i << 8);
                int rr = idx4 >> 3, kq = idx4 & 7;
                ra[i] = *(const float4*)&X[(size_t)(m0 + rr) * 512 + kb + (kq << 2)];
                rb[i] = *(const float4*)&W[(size_t)(n0 + rr) * 512 + kb + (kq << 2)];
            }
        }
        #pragma unroll 4
        for (int k = 0; k < 32; k++) {
            unsigned long long av[8], bv[4];
            ulonglong2 q;
            q = *(const ulonglong2*)&As2[k * 256 + tm * 16 + 0];  av[0] = q.x; av[1] = q.y;
            q = *(const ulonglong2*)&As2[k * 256 + tm * 16 + 4];  av[2] = q.x; av[3] = q.y;
            q = *(const ulonglong2*)&As2[k * 256 + tm * 16 + 8];  av[4] = q.x; av[5] = q.y;
            q = *(const ulonglong2*)&As2[k * 256 + tm * 16 + 12]; av[6] = q.x; av[7] = q.y;
            q = *(const ulonglong2*)&Bs[k * 128 + tn * 8 + 0];    bv[0] = q.x; bv[1] = q.y;
            q = *(const ulonglong2*)&Bs[k * 128 + tn * 8 + 4];    bv[2] = q.x; bv[3] = q.y;
            #pragma unroll
            for (int i = 0; i < 8; i++) {
                #pragma unroll
                for (int j = 0; j < 4; j++) FMA2(acc[i][j], av[i], bv[j]);
            }
        }
    }

    float4 bb0 = *(const float4*)&Bi[n0 + tn * 8];
    float4 bb1 = *(const float4*)&Bi[n0 + tn * 8 + 4];
    #pragma unroll
    for (int i = 0; i < 8; i++) {
        float* dst = &g_proj[(size_t)(m0 + tm * 8 + i) * NTOT + n0 + tn * 8];
        float4 o0, o1;
        o0.x = f2lo(acc[i][0]) + bb0.x; o0.y = f2hi(acc[i][0]) + bb0.y;
        o0.z = f2lo(acc[i][1]) + bb0.z; o0.w = f2hi(acc[i][1]) + bb0.w;
        o1.x = f2lo(acc[i][2]) + bb1.x; o1.y = f2hi(acc[i][2]) + bb1.y;
        o1.z = f2lo(acc[i][3]) + bb1.z; o1.w = f2hi(acc[i][3]) + bb1.w;
        *(float4*)dst = o0;
        *(float4*)(dst + 4) = o1;
    }
}

// ---------------------------------------------------------------------------
// Kernel B: persistent recurrence, 256 threads/CTA (8 warps).
// CTA cid owns output columns J=cid*4..cid*4+3 (20 w_state rows in SMEM).
// kh = tid>>7 selects k-half; within a half, thread (q=tid7>>5, u=(tid7>>2)&7,
// jl=tid7&3) computes partial dots for batches b0=2q+8u, b1=b0+1 (INTERLEAVED:
// warp q owns batch pairs {q,q+4,...,q+28} -> balanced live work under sorted
// lengths). Physical SMEM h slot for (q,u,v) = 16q + 2u + v (contiguous per
// warp -> warp-self-contained cp.async staging + R14 bank behavior).
// Partials kh1 -> kh0 via double-buffered sh_red (t-parity, stride 33);
// single full barrier per step; kh0-only barrier certifies h stores -> signal.
// ---------------------------------------------------------------------------
#define SH_HSTRIDE 516   // %32==4, conflict-free h rows, 16B-aligned stride
#define SH_WSTRIDE 520   // %32==8
#define OFF_W   (BDIM * SH_HSTRIDE)          // 33024
#define OFF_LEN (OFF_W + 20 * SH_WSTRIDE)    // 43424
#define OFF_RED (OFF_LEN + 64)               // 43488
#define SMEM_FLOATS_B (OFF_RED + 128 * 33)   // 47712 floats = 190848 B
#define NTHR_B 256

#define ISSUE_CHUNK(G) do {                                                   \
    if (ral) {                                                                \
        int _kb = k0 + ((G) << 6) + soff;                                     \
        const float* _s = hb + _kb;                                           \
        uint32_t _d = hd + (uint32_t)(_kb << 2);                              \
        _Pragma("unroll")                                                     \
        for (int _i = 0; _i < 8; _i++) cpasync16(_d + (_i << 4), _s + (_i << 2)); \
    }                                                                         \
    CP_COMMIT();                                                              \
} while (0)

#define COMPUTE_CHUNK(G) do {                                                 \
    if (anyact) {                                                             \
        _Pragma("unroll 8")                                                   \
        for (int _kq = 0; _kq < 16; _kq++) {                                  \
            int _k = k0 + ((G) << 6) + (_kq << 2);                            \
            ulonglong2 hv0 = *(const ulonglong2*)&h0[_k];                     \
            ulonglong2 hv1 = *(const ulonglong2*)&h1[_k];                     \
            _Pragma("unroll")                                                 \
            for (int _g = 0; _g < 5; _g++) {                                  \
                ulonglong2 wv =                                               \
                    *(const ulonglong2*)&sh_w[(_g * 4 + jl) * SH_WSTRIDE + _k]; \
                FMA2(acc0[_g], hv0.x, wv.x);                                  \
                FMA2(acc0[_g], hv0.y, wv.y);                                  \
                FMA2(acc1[_g], hv1.x, wv.x);                                  \
                FMA2(acc1[_g], hv1.y, wv.y);                                  \
            }                                                                 \
        }                                                                     \
    }                                                                         \
} while (0)

__global__ __launch_bounds__(NTHR_B, 1)
void lstm_kernel(const int* __restrict__ L, const float* __restrict__ Ws,
                 const float* __restrict__ bs, float* __restrict__ out)
{
    extern __shared__ float sm[];
    float* sh_h = sm;
    float* sh_w = sm + OFF_W;
    int*   sh_len = (int*)(sm + OFF_LEN);
    float* sh_red = sm + OFF_RED;     // [128][33]: 2 t-parity 11-float slots

    const int cid  = blockIdx.x;      // 0..127
    const int tid  = threadIdx.x;     // 0..255
    const int kh   = tid >> 7;        // k-half: 0 or 1
    const int tid7 = tid & 127;
    const int q    = tid7 >> 5;       // warp within half (0..3)
    const int u    = (tid7 >> 2) & 7; // pair index within warp (0..7)
    const int jl   = tid7 & 3;
    const int b0   = (q << 1) + (u << 3);   // interleaved: 2q + 8u
    const int b1   = b0 + 1;
    const int slot0 = (q << 4) + (u << 1);  // physical SMEM slot of b0
    const int J    = (cid << 2) + jl;
    const int k0   = kh << 8;         // 0 or 256
    const int mygrp = cid >> 4;

    const int lane = tid & 31;
    const int rl   = lane >> 1;                        // 0..15: slot offset
    const int sslot = (q << 4) + rl;                   // staged physical slot
    const int gsrow = (q << 1) + ((rl >> 1) << 3) + (rl & 1);  // its batch
    const int soff = (lane & 1) << 5;                  // 0/32 floats in chunk
    const uint32_t sh_h_u32 = (uint32_t)__cvta_generic_to_shared(sh_h);

    if (tid < BDIM) sh_len[tid] = read_len(L, tid);
    for (int i = tid; i < BDIM * SH_HSTRIDE; i += NTHR_B) sh_h[i] = 0.0f;
    for (int idx4 = tid; idx4 < 20 * 128; idx4 += NTHR_B) {
        int r = idx4 >> 7;
        int k = (idx4 & 127) << 2;
        int grow = ((r >> 2) << 9) + (cid << 2) + (r & 3);
        *(float4*)&sh_w[r * SH_WSTRIDE + k] = *(const float4*)&Ws[(size_t)grow * 512 + k];
    }
    __syncthreads();

    const int len0 = sh_len[b0];
    const int len1 = sh_len[b1];
    const int wlen = sh_len[q << 1];   // batch 2q = longest-lived in warp q
    const int slen = sh_len[gsrow];    // length of this lane's staged batch
    float bias[5];
    #pragma unroll
    for (int g = 0; g < 5; g++) bias[g] = bs[g * 512 + J];
    float c0 = 0.0f, c1 = 0.0f;

    const float* h0 = &sh_h[slot0 * SH_HSTRIDE];
    const float* h1 = &sh_h[(slot0 + 1) * SH_HSTRIDE];

    for (int t = 0; t < TDIM; t++) {
        const bool a0 = (t < len0);
        const bool a1 = (t < len1);
        const bool anyact = a0 | a1;   // == a0 (lengths sorted desc)

        // pi loads: only the epilogue half (kh0) needs them
        float pi0[6], pi1[6];
        if (kh == 0) {
            if (a0) {
                const float* p = &g_proj[(size_t)((b0 << 9) + t) * NTOT + J];
                #pragma unroll
                for (int g = 0; g < 6; g++) pi0[g] = p[g * 512];
            }
            if (a1) {
                const float* p = &g_proj[(size_t)((b1 << 9) + t) * NTOT + J];
                #pragma unroll
                for (int g = 0; g < 6; g++) pi1[g] = p[g * 512];
            }
        }

        unsigned long long acc0[5] = {}, acc1[5] = {};

        if (t > 0 && wlen > t) {
            const unsigned tgt = 16u * (unsigned)t;
            const bool ral = (slen > t);
            const float* hb = &g_hbuf[t & 1][gsrow << 9];
            const uint32_t hd = sh_h_u32 + (uint32_t)(sslot * SH_HSTRIDE) * 4u;
            unsigned* gc = &g_cnt[kh << 2];

            pollw(gc + 0, tgt); ISSUE_CHUNK(0);
            pollw(gc + 1, tgt); ISSUE_CHUNK(1);
            CP_WAITG(1); __syncwarp(); COMPUTE_CHUNK(0);
            pollw(gc + 2, tgt); ISSUE_CHUNK(2);
            CP_WAITG(1); __syncwarp(); COMPUTE_CHUNK(1);
            pollw(gc + 3, tgt); ISSUE_CHUNK(3);
            CP_WAITG(1); __syncwarp(); COMPUTE_CHUNK(2);
            CP_WAITG(0); __syncwarp(); COMPUTE_CHUNK(3);
        }
        // t == 0: h == 0 -> partials stay zero.

        if (kh == 1) {                     // publish partials (zeros if dead)
            float* r = &sh_red[tid7 * 33 + ((t & 1) << 4)];
            #pragma unroll
            for (int g = 0; g < 5; g++) {
                r[g]     = f2lo(acc0[g]) + f2hi(acc0[g]);
                r[5 + g] = f2lo(acc1[g]) + f2hi(acc1[g]);
            }
        }
        NBAR(1, NTHR_B);                   // single full barrier per step

        if (kh == 0) {
            const float* r = &sh_red[tid7 * 33 + ((t & 1) << 4)];
            float outv0 = 0.0f, outv1 = 0.0f;
            if (a0) {
                float ps[5];
                #pragma unroll
                for (int g = 0; g < 5; g++)
                    ps[g] = f2lo(acc0[g]) + f2hi(acc0[g]) + r[g] + bias[g];
                float ig = sigm(pi0[0] + ps[0]);
                float fg = sigm(pi0[1] + ps[1]);
                float gg = tanhf(pi0[2] + ps[2]);
                float og = sigm(pi0[3] + ps[3]);
                float cn = ig * gg + fg * c0;
                float ov = og * tanhf(cn);
                float hw = sigm(pi0[4] + ps[4]);
                outv0 = hw * ov + (1.0f - hw) * pi0[5];
                c0 = cn;
                __stcg(&g_hbuf[(t + 1) & 1][(b0 << 9) + J], outv0);
            } else c0 = 0.0f;
            if (a1) {
                float ps[5];
                #pragma unroll
                for (int g = 0; g < 5; g++)
                    ps[g] = f2lo(acc1[g]) + f2hi(acc1[g]) + r[5 + g] + bias[g];
                float ig = sigm(pi1[0] + ps[0]);
                float fg = sigm(pi1[1] + ps[1]);
                float gg = tanhf(pi1[2] + ps[2]);
                float og = sigm(pi1[3] + ps[3]);
                float cn = ig * gg + fg * c1;
                float ov = og * tanhf(cn);
                float hw = sigm(pi1[4] + ps[4]);
                outv1 = hw * ov + (1.0f - hw) * pi1[5];
                c1 = cn;
                __stcg(&g_hbuf[(t + 1) & 1][(b1 << 9) + J], outv1);
            } else c1 = 0.0f;
            out[(size_t)((b0 << 9) + t) * HDIM + J] = outv0;
            out[(size_t)((b1 << 9) + t) * HDIM + J] = outv1;

            NBAR(2, 128);                  // kh0 only: h stores certified
        }
        if (tid == 0 && t != TDIM - 1) signal_release(&g_cnt[mygrp]);
    }
}

// ---------------------------------------------------------------------------
__global__ void init_kernel()
{
    if (threadIdx.x < 8) g_cnt[threadIdx.x] = 0u;
}

extern "C" void kernel_launch(void* const* d_in, const int* in_sizes, int n_in,
                              void* d_out, int out_size)
{
    const float* x       = (const float*)d_in[0];
    const int*   lengths = (const int*)d_in[1];   // int32 or int64, auto-detected
    const float* w_in    = (const float*)d_in[2];
    const float* b_in    = (const float*)d_in[3];
    const float* w_state = (const float*)d_in[4];
    const float* b_state = (const float*)d_in[5];
    float* out = (float*)d_out;

    (void)in_sizes; (void)n_in; (void)out_size;

    init_kernel<<<1, 32>>>();

    dim3 gA(NTOT / 128, MTOT / 128);  // 24 x 256
    proj_kernel<<<gA, 256>>>(x, lengths, w_in, b_in);

    size_t smemB = (size_t)SMEM_FLOATS_B * sizeof(float);
    cudaFuncSetAttribute(lstm_kernel, cudaFuncAttributeMaxDynamicSharedMemorySize,
                         (int)smemB);
    lstm_kernel<<<NCTA_B, NTHR_B, smemB>>>(lengths, w_state, b_state, out);
}

// round 17
// speedup vs baseline: 1.2061x; 1.2061x over previous
#include <cuda_runtime.h>
#include <math.h>
#include <stdint.h>
#include <stddef.h>

// ---------------------------------------------------------------------------
// AugmentedLstm: B=64, T=512, D=512, H=512
//   Kernel A: proj = X[32768,512] @ w_in^T -> [32768,3072] (+bias), fp32 FFMA2
//   Kernel B: persistent 128-CTA recurrence, 256 thr/CTA (R14 base: k-half
//             split, 2 warps/SMSP, per-warp cp.async staging, contiguous
//             batch->warp map) + SPLIT EPILOGUE: kh0 finalizes b0, kh1
//             finalizes b1; cross partials via half-sized double-buffered
//             sh_red; per-half certification barriers + DUAL signals
//             (consumers poll 32*t). One full barrier per step remains.
// ---------------------------------------------------------------------------

#define BDIM 64
#define TDIM 512
#define HDIM 512
#define MTOT (BDIM * TDIM)   // 32768
#define NTOT (6 * HDIM)      // 3072
#define NCTA_B 128

// packed fp32x2 FMA (sm_100+/sm_103a PTX; ptxas never emits it from C++)
#define FMA2(d, a, b) asm("fma.rn.f32x2 %0, %1, %2, %0;" : "+l"(d) : "l"(a), "l"(b))

__device__ __forceinline__ float f2lo(unsigned long long v) {
    return __uint_as_float((unsigned)(v & 0xffffffffull));
}
__device__ __forceinline__ float f2hi(unsigned long long v) {
    return __uint_as_float((unsigned)(v >> 32));
}
__device__ __forceinline__ float sigm(float x) { return 1.0f / (1.0f + expf(-x)); }

// ---- global scratch (no runtime allocation allowed) ----
__device__ float g_proj[(size_t)MTOT * NTOT];     // 402 MB input projections
__device__ float g_hbuf[2][BDIM * HDIM];          // double-buffered h state
__device__ unsigned int g_cnt[8];                 // per-group step counters

__device__ __forceinline__ int read_len(const int* L, int b) {
    return (L[1] == 0) ? L[2 * b] : L[b];   // int64 vs int32 auto-detect
}

__device__ __forceinline__ void signal_release(unsigned* p) {
    unsigned t;
    asm volatile("atom.add.release.gpu.u32 %0, [%1], 1;" : "=r"(t) : "l"(p) : "memory");
}
__device__ __forceinline__ unsigned ld_acq(unsigned* p) {
    unsigned v;
    asm volatile("ld.acquire.gpu.u32 %0, [%1];" : "=r"(v) : "l"(p) : "memory");
    return v;
}
__device__ __forceinline__ void pollw(unsigned* p, unsigned tgt) {
    while ((int)(ld_acq(p) - tgt) < 0) { }
}

__device__ __forceinline__ void cpasync16(uint32_t dst, const float* src) {
    asm volatile("cp.async.cg.shared.global [%0], [%1], 16;" :: "r"(dst), "l"(src));
}
#define CP_COMMIT()  asm volatile("cp.async.commit_group;" ::: "memory")
#define CP_WAITG(n)  asm volatile("cp.async.wait_group " #n ";" ::: "memory")
#define NBAR(id, cnt) asm volatile("bar.sync %0, %1;" :: "r"(id), "r"(cnt) : "memory")

// ---------------------------------------------------------------------------
// Kernel A: 128x128 tile SGEMM with FFMA2 (A duplicated in SMEM so a2=(a,a))
// ---------------------------------------------------------------------------
__global__ __launch_bounds__(256)
void proj_kernel(const float* __restrict__ X, const int* __restrict__ L,
                 const float* __restrict__ W, const float* __restrict__ Bi)
{
    __shared__ float As2[32 * 256];   // [k][2*m] duplicated pairs
    __shared__ float Bs[32 * 128];    // [k][n]
    const int n0 = blockIdx.x * 128;
    const int m0 = blockIdx.y * 128;
    const int bidx = m0 >> 9;         // batch of this M tile (512 % 128 == 0)
    const int t0 = m0 & 511;
    if (read_len(L, bidx) <= t0) return;   // whole tile past this batch's length

    const int tid = threadIdx.x;
    const int tm = tid >> 4;          // 0..15
    const int tn = tid & 15;          // 0..15

    unsigned long long acc[8][4] = {};

    float4 ra[4], rb[4];
    #pragma unroll
    for (int i = 0; i < 4; i++) {     // prime chunk 0
        int idx4 = tid + (i << 8);
        int rr = idx4 >> 3, kq = idx4 & 7;
        ra[i] = *(const float4*)&X[(size_t)(m0 + rr) * 512 + (kq << 2)];
        rb[i] = *(const float4*)&W[(size_t)(n0 + rr) * 512 + (kq << 2)];
    }

    for (int kc = 0; kc < 16; kc++) {
        __syncthreads();
        #pragma unroll
        for (int i = 0; i < 4; i++) {
            int idx4 = tid + (i << 8);
            int rr = idx4 >> 3, kq = idx4 & 7;
            float4 v = ra[i];
            float2 d;
            d.x = v.x; d.y = v.x; *(float2*)&As2[((kq << 2) + 0) * 256 + 2 * rr] = d;
            d.x = v.y; d.y = v.y; *(float2*)&As2[((kq << 2) + 1) * 256 + 2 * rr] = d;
            d.x = v.z; d.y = v.z; *(float2*)&As2[((kq << 2) + 2) * 256 + 2 * rr] = d;
            d.x = v.w; d.y = v.w; *(float2*)&As2[((kq << 2) + 3) * 256 + 2 * rr] = d;
            float4 w4 = rb[i];
            Bs[((kq << 2) + 0) * 128 + rr] = w4.x;
            Bs[((kq << 2) + 1) * 128 + rr] = w4.y;
            Bs[((kq << 2) + 2) * 128 + rr] = w4.z;
            Bs[((kq << 2) + 3) * 128 + rr] = w4.w;
        }
        __syncthreads();
        if (kc < 15) {   // prefetch next chunk into registers during compute
            int kb = (kc + 1) << 5;
            #pragma unroll
            for (int i = 0; i < 4; i++) {
                int idx4 = tid + (i << 8);
                int rr = idx4 >> 3, kq = idx4 & 7;
                ra[i] = *(const float4*)&X[(size_t)(m0 + rr) * 512 + kb + (kq << 2)];
                rb[i] = *(const float4*)&W[(size_t)(n0 + rr) * 512 + kb + (kq << 2)];
            }
        }
        #pragma unroll 4
        for (int k = 0; k < 32; k++) {
            unsigned long long av[8], bv[4];
            ulonglong2 q;
            q = *(const ulonglong2*)&As2[k * 256 + tm * 16 + 0];  av[0] = q.x; av[1] = q.y;
            q = *(const ulonglong2*)&As2[k * 256 + tm * 16 + 4];  av[2] = q.x; av[3] = q.y;
            q = *(const ulonglong2*)&As2[k * 256 + tm * 16 + 8];  av[4] = q.x; av[5] = q.y;
            q = *(const ulonglong2*)&As2[k * 256 + tm * 16 + 12]; av[6] = q.x; av[7] = q.y;
            q = *(const ulonglong2*)&Bs[k * 128 + tn * 8 + 0];    bv[0] = q.x; bv[1] = q.y;
            q = *(const ulonglong2*)&Bs[k * 128 + tn * 8 + 4];    bv[2] = q.x; bv[3] = q.y;
            #pragma unroll
            for (int i = 0; i < 8; i++) {
                #pragma unroll
                for (int j = 0; j < 4; j++) FMA2(acc[i][j], av[i], bv[j]);
            }
        }
    }

    float4 bb0 = *(const float4*)&Bi[n0 + tn * 8];
    float4 bb1 = *(const float4*)&Bi[n0 + tn * 8 + 4];
    #pragma unroll
    for (int i = 0; i < 8; i++) {
        float* dst = &g_proj[(size_t)(m0 + tm * 8 + i) * NTOT + n0 + tn * 8];
        float4 o0, o1;
        o0.x = f2lo(acc[i][0]) + bb0.x; o0.y = f2hi(acc[i][0]) + bb0.y;
        o0.z = f2lo(acc[i][1]) + bb0.z; o0.w = f2hi(acc[i][1]) + bb0.w;
        o1.x = f2lo(acc[i][2]) + bb1.x; o1.y = f2hi(acc[i][2]) + bb1.y;
        o1.z = f2lo(acc[i][3]) + bb1.z; o1.w = f2hi(acc[i][3]) + bb1.w;
        *(float4*)dst = o0;
        *(float4*)(dst + 4) = o1;
    }
}

// ---------------------------------------------------------------------------
// Kernel B: persistent recurrence, 256 threads/CTA (8 warps), R14 mapping:
// kh = tid>>7 selects k-half; (bp=tid7>>2, jl=tid7&3) -> batches b0=2bp,
// b1=b0+1 (CONTIGUOUS: warp q owns batches 16q..16q+15 so whole warps retire
// as sorted lengths expire). Warp (kh,q) stages/consumes exactly its rows,
// 4-chunk cp.async pipeline, groups kh*4+0..3.
// SPLIT EPILOGUE: kh0 finalizes b0, kh1 finalizes b1. Each half publishes the
// OTHER batch's 5 partials (sh_red[tid*11 + 5*(t&1)], stride 11 conflict-
// free, t-parity double buffer), one full NBAR, then each half certifies its
// own h stores with a 128-thread barrier and signals (+2/CTA/step total;
// consumers poll 32*t).
// ---------------------------------------------------------------------------
#define SH_HSTRIDE 516   // %32==4, conflict-free h rows, 16B-aligned stride
#define SH_WSTRIDE 520   // %32==8
#define OFF_W   (BDIM * SH_HSTRIDE)          // 33024
#define OFF_LEN (OFF_W + 20 * SH_WSTRIDE)    // 43424
#define OFF_RED (OFF_LEN + 64)               // 43488
#define SMEM_FLOATS_B (OFF_RED + 256 * 11 + 16)  // 46320 floats = 185280 B
#define NTHR_B 256

#define ISSUE_CHUNK(G) do {                                                   \
    if (ral) {                                                                \
        int _kb = k0 + ((G) << 6) + soff;                                     \
        const float* _s = hb + _kb;                                           \
        uint32_t _d = hd + (uint32_t)(_kb << 2);                              \
        _Pragma("unroll")                                                     \
        for (int _i = 0; _i < 8; _i++) cpasync16(_d + (_i << 4), _s + (_i << 2)); \
    }                                                                         \
    CP_COMMIT();                                                              \
} while (0)

#define COMPUTE_CHUNK(G) do {                                                 \
    if (anyact) {                                                             \
        _Pragma("unroll 8")                                                   \
        for (int _kq = 0; _kq < 16; _kq++) {                                  \
            int _k = k0 + ((G) << 6) + (_kq << 2);                            \
            ulonglong2 hv0 = *(const ulonglong2*)&h0[_k];                     \
            ulonglong2 hv1 = *(const ulonglong2*)&h1[_k];                     \
            _Pragma("unroll")                                                 \
            for (int _g = 0; _g < 5; _g++) {                                  \
                ulonglong2 wv =                                               \
                    *(const ulonglong2*)&sh_w[(_g * 4 + jl) * SH_WSTRIDE + _k]; \
                FMA2(acc0[_g], hv0.x, wv.x);                                  \
                FMA2(acc0[_g], hv0.y, wv.y);                                  \
                FMA2(acc1[_g], hv1.x, wv.x);                                  \
                FMA2(acc1[_g], hv1.y, wv.y);                                  \
            }                                                                 \
        }                                                                     \
    }                                                                         \
} while (0)

__global__ __launch_bounds__(NTHR_B, 1)
void lstm_kernel(const int* __restrict__ L, const float* __restrict__ Ws,
                 const float* __restrict__ bs, float* __restrict__ out)
{
    extern __shared__ float sm[];
    float* sh_h = sm;
    float* sh_w = sm + OFF_W;
    int*   sh_len = (int*)(sm + OFF_LEN);
    float* sh_red = sm + OFF_RED;     // [256][11]: 2 t-parity 5-float slots

    const int cid  = blockIdx.x;      // 0..127
    const int tid  = threadIdx.x;     // 0..255
    const int kh   = tid >> 7;        // k-half: 0 or 1
    const int tid7 = tid & 127;
    const int bp   = tid7 >> 2;       // 0..31 (batch pair)
    const int jl   = tid7 & 3;
    const int b0   = bp << 1;
    const int b1   = b0 + 1;
    const int J    = (cid << 2) + jl;
    const int k0   = kh << 8;         // 0 or 256
    const int mygrp = cid >> 4;
    const int myb  = kh ? b1 : b0;    // batch this thread finalizes

    const int lane = tid & 31;
    const int q    = (tid >> 5) & 3;                   // warp within half
    const int srow = (q << 4) + (lane >> 1);           // staged/consumed row
    const int soff = (lane & 1) << 5;                  // 0/32 floats in chunk
    const uint32_t sh_h_u32 = (uint32_t)__cvta_generic_to_shared(sh_h);

    if (tid < BDIM) sh_len[tid] = read_len(L, tid);
    for (int i = tid; i < BDIM * SH_HSTRIDE; i += NTHR_B) sh_h[i] = 0.0f;
    for (int idx4 = tid; idx4 < 20 * 128; idx4 += NTHR_B) {
        int r = idx4 >> 7;
        int k = (idx4 & 127) << 2;
        int grow = ((r >> 2) << 9) + (cid << 2) + (r & 3);
        *(float4*)&sh_w[r * SH_WSTRIDE + k] = *(const float4*)&Ws[(size_t)grow * 512 + k];
    }
    __syncthreads();

    const int len0 = sh_len[b0];
    const int len1 = sh_len[b1];
    const int mylen = kh ? len1 : len0;
    const int wlen = sh_len[q << 4];   // longest length among this warp's rows
    const int slen = sh_len[srow];
    float bias[5];
    #pragma unroll
    for (int g = 0; g < 5; g++) bias[g] = bs[g * 512 + J];
    float c_my = 0.0f;                 // kh0: c of b0; kh1: c of b1

    const float* h0 = &sh_h[b0 * SH_HSTRIDE];
    const float* h1 = &sh_h[b1 * SH_HSTRIDE];

    for (int t = 0; t < TDIM; t++) {
        const bool a0 = (t < len0);
        const bool a1 = (t < len1);
        const bool anyact = a0 | a1;
        const bool amy = (t < mylen);

        // pi loads: each half loads only its finalized batch's projections
        float pi[6];
        if (amy) {
            const float* p = &g_proj[(size_t)((myb << 9) + t) * NTOT + J];
            #pragma unroll
            for (int g = 0; g < 6; g++) pi[g] = p[g * 512];
        }

        unsigned long long acc0[5] = {}, acc1[5] = {};

        if (t > 0 && wlen > t) {
            const unsigned tgt = 32u * (unsigned)t;
            const bool ral = (slen > t);
            const float* hb = &g_hbuf[t & 1][srow << 9];
            const uint32_t hd = sh_h_u32 + (uint32_t)(srow * SH_HSTRIDE) * 4u;
            unsigned* gc = &g_cnt[kh << 2];

            pollw(gc + 0, tgt); ISSUE_CHUNK(0);
            pollw(gc + 1, tgt); ISSUE_CHUNK(1);
            CP_WAITG(1); __syncwarp(); COMPUTE_CHUNK(0);
            pollw(gc + 2, tgt); ISSUE_CHUNK(2);
            CP_WAITG(1); __syncwarp(); COMPUTE_CHUNK(1);
            pollw(gc + 3, tgt); ISSUE_CHUNK(3);
            CP_WAITG(1); __syncwarp(); COMPUTE_CHUNK(2);
            CP_WAITG(0); __syncwarp(); COMPUTE_CHUNK(3);
        }
        // t == 0: h == 0 -> partials stay zero.

        // publish the OTHER batch's partials (kh0 -> b1's half0; kh1 -> b0's half1)
        {
            float* r = &sh_red[tid * 11 + 5 * (t & 1)];
            if (kh == 0) {
                #pragma unroll
                for (int g = 0; g < 5; g++) r[g] = f2lo(acc1[g]) + f2hi(acc1[g]);
            } else {
                #pragma unroll
                for (int g = 0; g < 5; g++) r[g] = f2lo(acc0[g]) + f2hi(acc0[g]);
            }
        }
        NBAR(1, NTHR_B);                   // the only full barrier per step

        // split epilogue: kh0 finalizes b0 (own acc0 + partner's half1),
        //                 kh1 finalizes b1 (own acc1 + partner's half0)
        {
            const float* r = &sh_red[(tid7 + (kh ? 0 : 128)) * 11 + 5 * (t & 1)];
            float outv = 0.0f;
            if (amy) {
                float ps[5];
                if (kh == 0) {
                    #pragma unroll
                    for (int g = 0; g < 5; g++)
                        ps[g] = f2lo(acc0[g]) + f2hi(acc0[g]) + r[g] + bias[g];
                } else {
                    #pragma unroll
                    for (int g = 0; g < 5; g++)
                        ps[g] = f2lo(acc1[g]) + f2hi(acc1[g]) + r[g] + bias[g];
                }
                float ig = sigm(pi[0] + ps[0]);
                float fg = sigm(pi[1] + ps[1]);
                float gg = tanhf(pi[2] + ps[2]);
                float og = sigm(pi[3] + ps[3]);
                float cn = ig * gg + fg * c_my;
                float ov = og * tanhf(cn);
                float hw = sigm(pi[4] + ps[4]);
                outv = hw * ov + (1.0f - hw) * pi[5];
                c_my = cn;
                __stcg(&g_hbuf[(t + 1) & 1][(myb << 9) + J], outv);
            } else {
                c_my = 0.0f;
            }
            out[(size_t)((myb << 9) + t) * HDIM + J] = outv;
        }

        // per-half certification + dual signals (run concurrently)
        NBAR(2 + kh, 128);
        if (tid7 == 0 && t != TDIM - 1) signal_release(&g_cnt[mygrp]);
    }
}

// ---------------------------------------------------------------------------
__global__ void init_kernel()
{
    if (threadIdx.x < 8) g_cnt[threadIdx.x] = 0u;
}

extern "C" void kernel_launch(void* const* d_in, const int* in_sizes, int n_in,
                              void* d_out, int out_size)
{
    const float* x       = (const float*)d_in[0];
    const int*   lengths = (const int*)d_in[1];   // int32 or int64, auto-detected
    const float* w_in    = (const float*)d_in[2];
    const float* b_in    = (const float*)d_in[3];
    const float* w_state = (const float*)d_in[4];
    const float* b_state = (const float*)d_in[5];
    float* out = (float*)d_out;

    (void)in_sizes; (void)n_in; (void)out_size;

    init_kernel<<<1, 32>>>();

    dim3 gA(NTOT / 128, MTOT / 128);  // 24 x 256
    proj_kernel<<<gA, 256>>>(x, lengths, w_in, b_in);

    size_t smemB = (size_t)SMEM_FLOATS_B * sizeof(float);
    cudaFuncSetAttribute(lstm_kernel, cudaFuncAttributeMaxDynamicSharedMemorySize,
                         (int)smemB);
    lstm_kernel<<<NCTA_B, NTHR_B, smemB>>>(lengths, w_state, b_state, out);
}